// round 5
// baseline (speedup 1.0000x reference)
#include <cuda_runtime.h>
#include <cuda_fp16.h>
#include <cstdint>

// ============================================================================
// CrossAttention: out = softmax((x Wq)(cond Wk)^T * s) (cond Wv) Wo + b
// B=2, SQ=SKV=2048, D_MODEL=1024, D_COND=768, H=16, DH=64
// R5: R3 baseline (mma.sync; tcgen05 unsupported by harness toolchain) +
//     f16x2 ex2 softmax (half the MUFU ops), 2-CTA/SM attention occupancy,
//     4x-ILP converts.
// ============================================================================

#define B_SZ    2
#define SQ      2048
#define SKV     2048
#define DMODEL  1024
#define DCOND   768
#define NHEADS  16
#define DHEAD   64
#define DATTN   1024
#define MROWS   (B_SZ * SQ)     // 4096

// --------------------------- scratch (device globals) -----------------------
__device__ __half g_xh [MROWS * DMODEL];
__device__ __half g_ch [MROWS * DCOND];
__device__ __half g_wq [DMODEL * DATTN];
__device__ __half g_wk [DCOND * DATTN];
__device__ __half g_wv [DCOND * DATTN];
__device__ __half g_wo [DATTN * DMODEL];
__device__ __half g_Q  [MROWS * DATTN];
__device__ __half g_K  [MROWS * DATTN];
__device__ __half g_V  [MROWS * DATTN];
__device__ __half g_AO [MROWS * DATTN];

// --------------------------- small helpers ----------------------------------
__device__ __forceinline__ uint32_t smem_u32(const void* p) {
    return (uint32_t)__cvta_generic_to_shared(p);
}
__device__ __forceinline__ void cp16(uint32_t dst, const void* src) {
    asm volatile("cp.async.cg.shared.global [%0], [%1], 16;" :: "r"(dst), "l"(src));
}
__device__ __forceinline__ void cp_commit() {
    asm volatile("cp.async.commit_group;");
}
template<int N> __device__ __forceinline__ void cp_wait() {
    asm volatile("cp.async.wait_group %0;" :: "n"(N));
}
__device__ __forceinline__ void ldsm4(uint32_t* r, uint32_t addr) {
    asm volatile("ldmatrix.sync.aligned.m8n8.x4.shared.b16 {%0,%1,%2,%3}, [%4];"
                 : "=r"(r[0]), "=r"(r[1]), "=r"(r[2]), "=r"(r[3]) : "r"(addr));
}
__device__ __forceinline__ void ldsm4t(uint32_t* r, uint32_t addr) {
    asm volatile("ldmatrix.sync.aligned.m8n8.x4.trans.shared.b16 {%0,%1,%2,%3}, [%4];"
                 : "=r"(r[0]), "=r"(r[1]), "=r"(r[2]), "=r"(r[3]) : "r"(addr));
}
__device__ __forceinline__ void mma16816(float* c, const uint32_t* a, const uint32_t* b) {
    asm volatile(
        "mma.sync.aligned.m16n8k16.row.col.f32.f16.f16.f32 "
        "{%0,%1,%2,%3}, {%4,%5,%6,%7}, {%8,%9}, {%0,%1,%2,%3};"
        : "+f"(c[0]), "+f"(c[1]), "+f"(c[2]), "+f"(c[3])
        : "r"(a[0]), "r"(a[1]), "r"(a[2]), "r"(a[3]), "r"(b[0]), "r"(b[1]));
}
__device__ __forceinline__ float ex2(float x) {
    float r; asm("ex2.approx.ftz.f32 %0, %1;" : "=f"(r) : "f"(x)); return r;
}
// pack (a-m, b-m) to half2, exp2 in f16x2, return bits + accumulate f32 sum
__device__ __forceinline__ uint32_t exp2pack(float a, float b, float m, float& rs) {
    __half2 h = h2exp2(__floats2half2_rn(a - m, b - m));
    float2 f = __half22float2(h);
    rs += f.x + f.y;
    return *reinterpret_cast<uint32_t*>(&h);
}

// --------------------------- fp32 -> fp16 convert (4x ILP) -------------------
__global__ void f2h_kernel(const float* __restrict__ s, __half* __restrict__ d,
                           int n, float scale) {
    int i = (blockIdx.x * blockDim.x * 4 + threadIdx.x) * 4;
    #pragma unroll
    for (int u = 0; u < 4; u++, i += blockDim.x * 4) {
        if (i < n) {
            float4 v = *reinterpret_cast<const float4*>(s + i);
            *reinterpret_cast<__half2*>(d + i)     = __floats2half2_rn(v.x * scale, v.y * scale);
            *reinterpret_cast<__half2*>(d + i + 2) = __floats2half2_rn(v.z * scale, v.w * scale);
        }
    }
}

// --------------------------- HMMA GEMM (2-stage cp.async pipeline) ----------
// C[M,N] = A[M,K] @ W[K,N]. Block 128x128x32, 256 threads, 8 warps (2x4).
template<int OUTF32, int HASBIAS, int KVMODE>
__global__ __launch_bounds__(256)
void gemm_hmma(const __half* __restrict__ A,
               const __half* __restrict__ W0, const __half* __restrict__ W1,
               void* __restrict__ C0, void* __restrict__ C1,
               const float* __restrict__ bias, int M, int N, int K) {
    __shared__ __half As[2][128 * 40];
    __shared__ __half Bs[2][32 * 136];

    const __half* W = (KVMODE && blockIdx.z) ? W1 : W0;
    void* C         = (KVMODE && blockIdx.z) ? C1 : C0;

    const int tid  = threadIdx.x;
    const int lane = tid & 31;
    const int wid  = tid >> 5;
    const int wm   = wid >> 2;
    const int wn   = wid & 3;
    const int brow = blockIdx.y * 128;
    const int bcol = blockIdx.x * 128;

    const int ar = tid >> 2, ac = (tid & 3) * 8;
    const int br = tid >> 4, bc = (tid & 15) * 8;

    auto loadTile = [&](int kt, int buf) {
        #pragma unroll
        for (int i = 0; i < 2; i++) {
            int r = ar + i * 64;
            cp16(smem_u32(&As[buf][r * 40 + ac]),
                 &A[(size_t)(brow + r) * K + kt + ac]);
        }
        #pragma unroll
        for (int i = 0; i < 2; i++) {
            int r = br + i * 16;
            cp16(smem_u32(&Bs[buf][r * 136 + bc]),
                 &W[(size_t)(kt + r) * N + bcol + bc]);
        }
    };

    float acc[4][4][4];
    #pragma unroll
    for (int i = 0; i < 4; i++)
        #pragma unroll
        for (int j = 0; j < 4; j++)
            #pragma unroll
            for (int k = 0; k < 4; k++) acc[i][j][k] = 0.f;

    const int a_r = wm * 64 + (lane & 7) + (lane & 8);
    const int a_c = (lane & 16) >> 1;
    const int b_k = (lane & 7) + (lane & 8);
    const int b_n = wn * 32 + ((lane & 16) >> 1);

    const int T = K / 32;
    loadTile(0, 0);
    cp_commit();

    for (int t = 0; t < T; t++) {
        if (t + 1 < T) { loadTile((t + 1) * 32, (t + 1) & 1); cp_commit(); cp_wait<1>(); }
        else           { cp_wait<0>(); }
        __syncthreads();

        const uint32_t asm_b = smem_u32(As[t & 1]);
        const uint32_t bsm_b = smem_u32(Bs[t & 1]);
        #pragma unroll
        for (int ks = 0; ks < 2; ks++) {
            uint32_t af[4][4], bf[4][2];
            #pragma unroll
            for (int mt = 0; mt < 4; mt++)
                ldsm4(af[mt], asm_b + (uint32_t)(((a_r + mt * 16) * 40 + ks * 16 + a_c) * 2));
            #pragma unroll
            for (int ntp = 0; ntp < 2; ntp++) {
                uint32_t r[4];
                ldsm4t(r, bsm_b + (uint32_t)(((ks * 16 + b_k) * 136 + b_n + ntp * 16) * 2));
                bf[ntp * 2][0] = r[0]; bf[ntp * 2][1] = r[1];
                bf[ntp * 2 + 1][0] = r[2]; bf[ntp * 2 + 1][1] = r[3];
            }
            #pragma unroll
            for (int mt = 0; mt < 4; mt++)
                #pragma unroll
                for (int nt = 0; nt < 4; nt++)
                    mma16816(acc[mt][nt], af[mt], bf[nt]);
        }
        __syncthreads();
    }

    const int er = brow + wm * 64 + (lane >> 2);
    const int ec = bcol + wn * 32 + 2 * (lane & 3);
    #pragma unroll
    for (int mt = 0; mt < 4; mt++) {
        #pragma unroll
        for (int nt = 0; nt < 4; nt++) {
            int r0 = er + mt * 16;
            int c  = ec + nt * 8;
            if (OUTF32) {
                float* O = (float*)C;
                float b0 = HASBIAS ? bias[c]     : 0.f;
                float b1 = HASBIAS ? bias[c + 1] : 0.f;
                O[(size_t)r0 * N + c]           = acc[mt][nt][0] + b0;
                O[(size_t)r0 * N + c + 1]       = acc[mt][nt][1] + b1;
                O[(size_t)(r0 + 8) * N + c]     = acc[mt][nt][2] + b0;
                O[(size_t)(r0 + 8) * N + c + 1] = acc[mt][nt][3] + b1;
            } else {
                __half* O = (__half*)C;
                *reinterpret_cast<__half2*>(&O[(size_t)r0 * N + c]) =
                    __floats2half2_rn(acc[mt][nt][0], acc[mt][nt][1]);
                *reinterpret_cast<__half2*>(&O[(size_t)(r0 + 8) * N + c]) =
                    __floats2half2_rn(acc[mt][nt][2], acc[mt][nt][3]);
            }
        }
    }
}

// --------------------------- flash attention ---------------------------------
// grid (SQ/128, H, B), 256 threads (8 warps), warp -> 16 q rows.
// KV tile 64 double-buffered (cp.async). Q pre-scaled by 0.125*log2e, softmax
// in log2 domain with f16x2 ex2. Static smem 36864B, 2 CTAs/SM.
__global__ __launch_bounds__(256, 2)
void flash_attn(const __half* __restrict__ Qg, const __half* __restrict__ Kg,
                const __half* __restrict__ Vg, __half* __restrict__ Og) {
    __shared__ __half sm[2 * 9216];   // 36864 B

    const int tid  = threadIdx.x;
    const int lane = tid & 31;
    const int warp = tid >> 5;
    const int b = blockIdx.z, h = blockIdx.y;
    const int q0 = blockIdx.x * 128;

    auto Kbuf = [&](int p) { return sm + p * 9216; };
    auto Vbuf = [&](int p) { return sm + p * 9216 + 4608; };

    auto loadKV = [&](int kv0, int p) {
        __half* kd = Kbuf(p);
        __half* vd = Vbuf(p);
        #pragma unroll
        for (int i = tid; i < 1024; i += 256) {
            int mat = i >> 9, idx = i & 511;
            int r = idx >> 3, c = (idx & 7) * 8;
            const __half* src = (mat ? Vg : Kg) +
                (size_t)(b * SKV + kv0 + r) * DATTN + h * DHEAD + c;
            __half* dst = (mat ? vd : kd) + r * 72 + c;
            cp16(smem_u32(dst), src);
        }
    };

    // stage Q in sm[0..9216), extract fragments, release for KV buffers
    for (int i = tid; i < 1024; i += 256) {
        int r = i >> 3, c = (i & 7) * 8;
        *reinterpret_cast<uint4*>(&sm[r * 72 + c]) =
            *reinterpret_cast<const uint4*>(
                &Qg[(size_t)(b * SQ + q0 + r) * DATTN + h * DHEAD + c]);
    }
    __syncthreads();

    const int a_r  = warp * 16 + (lane & 7) + (lane & 8);
    const int a_c  = (lane & 16) >> 1;
    const int kb_n = (lane & 7) + ((lane & 16) >> 1);
    const int kb_c = (lane & 8);
    const int vb_k = (lane & 7) + (lane & 8);
    const int vb_d = (lane & 16) >> 1;

    uint32_t qf[4][4];
    const uint32_t qsm = smem_u32(sm);
    #pragma unroll
    for (int ks = 0; ks < 4; ks++)
        ldsm4(qf[ks], qsm + (uint32_t)((a_r * 72 + ks * 16 + a_c) * 2));
    __syncthreads();

    loadKV(0, 0);
    cp_commit();

    float of[8][4];
    #pragma unroll
    for (int i = 0; i < 8; i++) { of[i][0]=of[i][1]=of[i][2]=of[i][3]=0.f; }
    float m0 = -1e30f, m1 = -1e30f, l0 = 0.f, l1 = 0.f;

    const int NIT = SKV / 64;
    for (int it = 0; it < NIT; it++) {
        if (it + 1 < NIT) { loadKV((it + 1) * 64, (it + 1) & 1); cp_commit(); cp_wait<1>(); }
        else              { cp_wait<0>(); }
        __syncthreads();

        const uint32_t ksm = smem_u32(Kbuf(it & 1));
        const uint32_t vsm = smem_u32(Vbuf(it & 1));

        // S = Q K^T (log2 units, pre-scaled)
        float sf[8][4];
        #pragma unroll
        for (int i = 0; i < 8; i++) { sf[i][0]=sf[i][1]=sf[i][2]=sf[i][3]=0.f; }
        #pragma unroll
        for (int ks = 0; ks < 4; ks++) {
            uint32_t bf[8][2];
            #pragma unroll
            for (int ntp = 0; ntp < 4; ntp++) {
                uint32_t r[4];
                ldsm4(r, ksm + (uint32_t)(((ntp * 16 + kb_n) * 72 + ks * 16 + kb_c) * 2));
                bf[ntp * 2][0] = r[0]; bf[ntp * 2][1] = r[1];
                bf[ntp * 2 + 1][0] = r[2]; bf[ntp * 2 + 1][1] = r[3];
            }
            #pragma unroll
            for (int nt = 0; nt < 8; nt++) mma16816(sf[nt], qf[ks], bf[nt]);
        }

        // online softmax (log2 domain, f16x2 exp)
        float mx0 = -1e30f, mx1 = -1e30f;
        #pragma unroll
        for (int nt = 0; nt < 8; nt++) {
            mx0 = fmaxf(mx0, fmaxf(sf[nt][0], sf[nt][1]));
            mx1 = fmaxf(mx1, fmaxf(sf[nt][2], sf[nt][3]));
        }
        #pragma unroll
        for (int off = 1; off < 4; off <<= 1) {
            mx0 = fmaxf(mx0, __shfl_xor_sync(0xffffffffu, mx0, off));
            mx1 = fmaxf(mx1, __shfl_xor_sync(0xffffffffu, mx1, off));
        }
        float mn0 = fmaxf(m0, mx0), mn1 = fmaxf(m1, mx1);
        float al0 = ex2(m0 - mn0), al1 = ex2(m1 - mn1);

        // P = exp2(S - m) in f16x2, packed directly as PV A-fragments
        uint32_t ph[16];
        float rs0 = 0.f, rs1 = 0.f;
        #pragma unroll
        for (int j = 0; j < 4; j++) {
            ph[4 * j + 0] = exp2pack(sf[2 * j][0],     sf[2 * j][1],     mn0, rs0);
            ph[4 * j + 1] = exp2pack(sf[2 * j][2],     sf[2 * j][3],     mn1, rs1);
            ph[4 * j + 2] = exp2pack(sf[2 * j + 1][0], sf[2 * j + 1][1], mn0, rs0);
            ph[4 * j + 3] = exp2pack(sf[2 * j + 1][2], sf[2 * j + 1][3], mn1, rs1);
        }
        #pragma unroll
        for (int off = 1; off < 4; off <<= 1) {
            rs0 += __shfl_xor_sync(0xffffffffu, rs0, off);
            rs1 += __shfl_xor_sync(0xffffffffu, rs1, off);
        }
        l0 = l0 * al0 + rs0; m0 = mn0;
        l1 = l1 * al1 + rs1; m1 = mn1;
        #pragma unroll
        for (int dt = 0; dt < 8; dt++) {
            of[dt][0] *= al0; of[dt][1] *= al0; of[dt][2] *= al1; of[dt][3] *= al1;
        }

        // O += P V
        #pragma unroll
        for (int j = 0; j < 4; j++) {
            uint32_t bf[8][2];
            #pragma unroll
            for (int p = 0; p < 4; p++) {
                uint32_t r[4];
                ldsm4t(r, vsm + (uint32_t)(((j * 16 + vb_k) * 72 + p * 16 + vb_d) * 2));
                bf[p * 2][0] = r[0]; bf[p * 2][1] = r[1];
                bf[p * 2 + 1][0] = r[2]; bf[p * 2 + 1][1] = r[3];
            }
            #pragma unroll
            for (int dt = 0; dt < 8; dt++) mma16816(of[dt], &ph[4 * j], bf[dt]);
        }
        __syncthreads();
    }

    float inv0 = 1.f / l0, inv1 = 1.f / l1;
    const int r0 = b * SQ + q0 + warp * 16 + (lane >> 2);
    const int cb = h * DHEAD + 2 * (lane & 3);
    #pragma unroll
    for (int dt = 0; dt < 8; dt++) {
        int c = cb + dt * 8;
        *reinterpret_cast<__half2*>(&Og[(size_t)r0 * DATTN + c]) =
            __floats2half2_rn(of[dt][0] * inv0, of[dt][1] * inv0);
        *reinterpret_cast<__half2*>(&Og[(size_t)(r0 + 8) * DATTN + c]) =
            __floats2half2_rn(of[dt][2] * inv1, of[dt][3] * inv1);
    }
}

// --------------------------- launch ------------------------------------------
extern "C" void kernel_launch(void* const* d_in, const int* in_sizes, int n_in,
                              void* d_out, int out_size) {
    (void)in_sizes; (void)n_in; (void)out_size;
    const float* x    = (const float*)d_in[0];
    const float* cond = (const float*)d_in[1];
    const float* wq   = (const float*)d_in[2];
    const float* wk   = (const float*)d_in[3];
    const float* wv   = (const float*)d_in[4];
    const float* wo   = (const float*)d_in[5];
    const float* bo   = (const float*)d_in[6];

    __half *xh, *ch, *wqh, *wkh, *wvh, *woh, *Qb, *Kb, *Vb, *AOb;
    cudaGetSymbolAddress((void**)&xh,  g_xh);
    cudaGetSymbolAddress((void**)&ch,  g_ch);
    cudaGetSymbolAddress((void**)&wqh, g_wq);
    cudaGetSymbolAddress((void**)&wkh, g_wk);
    cudaGetSymbolAddress((void**)&wvh, g_wv);
    cudaGetSymbolAddress((void**)&woh, g_wo);
    cudaGetSymbolAddress((void**)&Qb,  g_Q);
    cudaGetSymbolAddress((void**)&Kb,  g_K);
    cudaGetSymbolAddress((void**)&Vb,  g_V);
    cudaGetSymbolAddress((void**)&AOb, g_AO);

    const float QSCALE = 0.125f * 1.44269504088896f;  // d^-0.5 * log2(e)
    auto cvt = [&](const float* s, __half* d, int n, float sc) {
        f2h_kernel<<<(n / 16 + 255) / 256, 256>>>(s, d, n, sc);
    };
    cvt(x,    xh,  MROWS * DMODEL, 1.f);
    cvt(cond, ch,  MROWS * DCOND,  1.f);
    cvt(wq,   wqh, DMODEL * DATTN, QSCALE);
    cvt(wk,   wkh, DCOND * DATTN,  1.f);
    cvt(wv,   wvh, DCOND * DATTN,  1.f);
    cvt(wo,   woh, DATTN * DMODEL, 1.f);

    dim3 gq(DATTN / 128, MROWS / 128, 1);     // (8, 32)
    gemm_hmma<0, 0, 0><<<gq, 256>>>(xh, wqh, nullptr, Qb, nullptr, nullptr,
                                    MROWS, DATTN, DMODEL);
    dim3 gkv(DATTN / 128, MROWS / 128, 2);    // (8, 32, 2)
    gemm_hmma<0, 0, 1><<<gkv, 256>>>(ch, wkh, wvh, Kb, Vb, nullptr,
                                     MROWS, DATTN, DCOND);

    flash_attn<<<dim3(SQ / 128, NHEADS, B_SZ), 256>>>(Qb, Kb, Vb, AOb);

    dim3 gout(DMODEL / 128, MROWS / 128, 1);
    gemm_hmma<1, 1, 0><<<gout, 256>>>(AOb, woh, nullptr, d_out, nullptr, bo,
                                      MROWS, DMODEL, DATTN);
}

// round 7
// speedup vs baseline: 1.0808x; 1.0808x over previous
#include <cuda_runtime.h>
#include <cuda_fp16.h>
#include <cstdint>

// ============================================================================
// CrossAttention: out = softmax((x Wq)(cond Wk)^T * s) (cond Wv) Wo + b
// B=2, SQ=SKV=2048, D_MODEL=1024, D_COND=768, H=16, DH=64
// R7: R3 proven attention + GEMM cores; merged single convert launch;
//     Q/K/V projections fused into one launch (grid.z selects source/weight).
// ============================================================================

#define B_SZ    2
#define SQ      2048
#define SKV     2048
#define DMODEL  1024
#define DCOND   768
#define NHEADS  16
#define DHEAD   64
#define DATTN   1024
#define MROWS   (B_SZ * SQ)     // 4096

// --------------------------- scratch (device globals) -----------------------
__device__ __half g_xh [MROWS * DMODEL];
__device__ __half g_ch [MROWS * DCOND];
__device__ __half g_wq [DMODEL * DATTN];
__device__ __half g_wk [DCOND * DATTN];
__device__ __half g_wv [DCOND * DATTN];
__device__ __half g_wo [DATTN * DMODEL];
__device__ __half g_Q  [MROWS * DATTN];
__device__ __half g_K  [MROWS * DATTN];
__device__ __half g_V  [MROWS * DATTN];
__device__ __half g_AO [MROWS * DATTN];

// --------------------------- small helpers ----------------------------------
__device__ __forceinline__ uint32_t smem_u32(const void* p) {
    return (uint32_t)__cvta_generic_to_shared(p);
}
__device__ __forceinline__ void cp16(uint32_t dst, const void* src) {
    asm volatile("cp.async.cg.shared.global [%0], [%1], 16;" :: "r"(dst), "l"(src));
}
__device__ __forceinline__ void cp_commit() {
    asm volatile("cp.async.commit_group;");
}
template<int N> __device__ __forceinline__ void cp_wait() {
    asm volatile("cp.async.wait_group %0;" :: "n"(N));
}
__device__ __forceinline__ void ldsm4(uint32_t* r, uint32_t addr) {
    asm volatile("ldmatrix.sync.aligned.m8n8.x4.shared.b16 {%0,%1,%2,%3}, [%4];"
                 : "=r"(r[0]), "=r"(r[1]), "=r"(r[2]), "=r"(r[3]) : "r"(addr));
}
__device__ __forceinline__ void ldsm4t(uint32_t* r, uint32_t addr) {
    asm volatile("ldmatrix.sync.aligned.m8n8.x4.trans.shared.b16 {%0,%1,%2,%3}, [%4];"
                 : "=r"(r[0]), "=r"(r[1]), "=r"(r[2]), "=r"(r[3]) : "r"(addr));
}
__device__ __forceinline__ void mma16816(float* c, const uint32_t* a, const uint32_t* b) {
    asm volatile(
        "mma.sync.aligned.m16n8k16.row.col.f32.f16.f16.f32 "
        "{%0,%1,%2,%3}, {%4,%5,%6,%7}, {%8,%9}, {%0,%1,%2,%3};"
        : "+f"(c[0]), "+f"(c[1]), "+f"(c[2]), "+f"(c[3])
        : "r"(a[0]), "r"(a[1]), "r"(a[2]), "r"(a[3]), "r"(b[0]), "r"(b[1]));
}
__device__ __forceinline__ uint32_t pack_h2(float a, float b) {
    __half2 h = __floats2half2_rn(a, b);
    return *reinterpret_cast<uint32_t*>(&h);
}
__device__ __forceinline__ float ex2(float x) {
    float r; asm("ex2.approx.ftz.f32 %0, %1;" : "=f"(r) : "f"(x)); return r;
}

// --------------------------- merged fp32 -> fp16 convert ---------------------
#define C_N0  (MROWS * DMODEL / 4)
#define C_N1  (C_N0 + MROWS * DCOND / 4)
#define C_N2  (C_N1 + DMODEL * DATTN / 4)
#define C_N3  (C_N2 + DCOND * DATTN / 4)
#define C_N4  (C_N3 + DCOND * DATTN / 4)
#define C_N5  (C_N4 + DATTN * DMODEL / 4)

__global__ void convert_all(const float* __restrict__ x, const float* __restrict__ cond,
                            const float* __restrict__ wq, const float* __restrict__ wk,
                            const float* __restrict__ wv, const float* __restrict__ wo,
                            __half* __restrict__ xh, __half* __restrict__ ch,
                            __half* __restrict__ wqh, __half* __restrict__ wkh,
                            __half* __restrict__ wvh, __half* __restrict__ woh,
                            float qscale) {
    int i4 = blockIdx.x * blockDim.x + threadIdx.x;
    if (i4 >= C_N5) return;
    const float* s; __half* d; int off; float sc = 1.f;
    if      (i4 < C_N0) { s = x;    d = xh;  off = i4; }
    else if (i4 < C_N1) { s = cond; d = ch;  off = i4 - C_N0; }
    else if (i4 < C_N2) { s = wq;   d = wqh; off = i4 - C_N1; sc = qscale; }
    else if (i4 < C_N3) { s = wk;   d = wkh; off = i4 - C_N2; }
    else if (i4 < C_N4) { s = wv;   d = wvh; off = i4 - C_N3; }
    else                { s = wo;   d = woh; off = i4 - C_N4; }
    float4 v = *reinterpret_cast<const float4*>(s + off * 4);
    *reinterpret_cast<__half2*>(d + off * 4)     = __floats2half2_rn(v.x * sc, v.y * sc);
    *reinterpret_cast<__half2*>(d + off * 4 + 2) = __floats2half2_rn(v.z * sc, v.w * sc);
}

// --------------------------- HMMA GEMM (2-stage cp.async pipeline) ----------
// C[M,N] = A[M,K] @ W[K,N]. Block 128x128x32, 256 threads, 8 warps (2x4).
// QKVMODE: blockIdx.z in {0,1,2} selects (A0,W0,C0,K0) / (A1,W1,C1,K1) /
// (A1,W2,C2,K1) — the fused Q/K/V projection launch.
template<int OUTF32, int HASBIAS, int QKVMODE>
__global__ __launch_bounds__(256)
void gemm_hmma(const __half* __restrict__ A0, const __half* __restrict__ A1,
               const __half* __restrict__ W0, const __half* __restrict__ W1,
               const __half* __restrict__ W2,
               void* __restrict__ C0, void* __restrict__ C1, void* __restrict__ C2,
               const float* __restrict__ bias, int M, int N, int K0, int K1) {
    __shared__ __half As[2][128 * 40];
    __shared__ __half Bs[2][32 * 136];

    const __half* A = A0;
    const __half* W = W0;
    void* C = C0;
    int K = K0;
    if (QKVMODE) {
        if (blockIdx.z == 1)      { A = A1; W = W1; C = C1; K = K1; }
        else if (blockIdx.z == 2) { A = A1; W = W2; C = C2; K = K1; }
    }

    const int tid  = threadIdx.x;
    const int lane = tid & 31;
    const int wid  = tid >> 5;
    const int wm   = wid >> 2;
    const int wn   = wid & 3;
    const int brow = blockIdx.y * 128;
    const int bcol = blockIdx.x * 128;

    const int ar = tid >> 2, ac = (tid & 3) * 8;
    const int br = tid >> 4, bc = (tid & 15) * 8;

    auto loadTile = [&](int kt, int buf) {
        #pragma unroll
        for (int i = 0; i < 2; i++) {
            int r = ar + i * 64;
            cp16(smem_u32(&As[buf][r * 40 + ac]),
                 &A[(size_t)(brow + r) * K + kt + ac]);
        }
        #pragma unroll
        for (int i = 0; i < 2; i++) {
            int r = br + i * 16;
            cp16(smem_u32(&Bs[buf][r * 136 + bc]),
                 &W[(size_t)(kt + r) * N + bcol + bc]);
        }
    };

    float acc[4][4][4];
    #pragma unroll
    for (int i = 0; i < 4; i++)
        #pragma unroll
        for (int j = 0; j < 4; j++)
            #pragma unroll
            for (int k = 0; k < 4; k++) acc[i][j][k] = 0.f;

    const int a_r = wm * 64 + (lane & 7) + (lane & 8);
    const int a_c = (lane & 16) >> 1;
    const int b_k = (lane & 7) + (lane & 8);
    const int b_n = wn * 32 + ((lane & 16) >> 1);

    const int T = K / 32;
    loadTile(0, 0);
    cp_commit();

    for (int t = 0; t < T; t++) {
        if (t + 1 < T) { loadTile((t + 1) * 32, (t + 1) & 1); cp_commit(); cp_wait<1>(); }
        else           { cp_wait<0>(); }
        __syncthreads();

        const uint32_t asm_b = smem_u32(As[t & 1]);
        const uint32_t bsm_b = smem_u32(Bs[t & 1]);
        #pragma unroll
        for (int ks = 0; ks < 2; ks++) {
            uint32_t af[4][4], bf[4][2];
            #pragma unroll
            for (int mt = 0; mt < 4; mt++)
                ldsm4(af[mt], asm_b + (uint32_t)(((a_r + mt * 16) * 40 + ks * 16 + a_c) * 2));
            #pragma unroll
            for (int ntp = 0; ntp < 2; ntp++) {
                uint32_t r[4];
                ldsm4t(r, bsm_b + (uint32_t)(((ks * 16 + b_k) * 136 + b_n + ntp * 16) * 2));
                bf[ntp * 2][0] = r[0]; bf[ntp * 2][1] = r[1];
                bf[ntp * 2 + 1][0] = r[2]; bf[ntp * 2 + 1][1] = r[3];
            }
            #pragma unroll
            for (int mt = 0; mt < 4; mt++)
                #pragma unroll
                for (int nt = 0; nt < 4; nt++)
                    mma16816(acc[mt][nt], af[mt], bf[nt]);
        }
        __syncthreads();
    }

    const int er = brow + wm * 64 + (lane >> 2);
    const int ec = bcol + wn * 32 + 2 * (lane & 3);
    #pragma unroll
    for (int mt = 0; mt < 4; mt++) {
        #pragma unroll
        for (int nt = 0; nt < 4; nt++) {
            int r0 = er + mt * 16;
            int c  = ec + nt * 8;
            if (OUTF32) {
                float* O = (float*)C;
                float b0 = HASBIAS ? bias[c]     : 0.f;
                float b1 = HASBIAS ? bias[c + 1] : 0.f;
                O[(size_t)r0 * N + c]           = acc[mt][nt][0] + b0;
                O[(size_t)r0 * N + c + 1]       = acc[mt][nt][1] + b1;
                O[(size_t)(r0 + 8) * N + c]     = acc[mt][nt][2] + b0;
                O[(size_t)(r0 + 8) * N + c + 1] = acc[mt][nt][3] + b1;
            } else {
                __half* O = (__half*)C;
                *reinterpret_cast<__half2*>(&O[(size_t)r0 * N + c]) =
                    __floats2half2_rn(acc[mt][nt][0], acc[mt][nt][1]);
                *reinterpret_cast<__half2*>(&O[(size_t)(r0 + 8) * N + c]) =
                    __floats2half2_rn(acc[mt][nt][2], acc[mt][nt][3]);
            }
        }
    }
}

// --------------------------- flash attention (exact R3) ----------------------
// grid (SQ/128, H, B), 256 threads (8 warps), warp -> 16 q rows.
// KV tile 64 double-buffered. Q pre-scaled by 0.125*log2e; fp32 ex2 softmax.
__global__ __launch_bounds__(256)
void flash_attn(const __half* __restrict__ Qg, const __half* __restrict__ Kg,
                const __half* __restrict__ Vg, __half* __restrict__ Og) {
    __shared__ __half sm[2 * 9216];   // 36864 B

    const int tid  = threadIdx.x;
    const int lane = tid & 31;
    const int warp = tid >> 5;
    const int b = blockIdx.z, h = blockIdx.y;
    const int q0 = blockIdx.x * 128;

    auto Kbuf = [&](int p) { return sm + p * 9216; };
    auto Vbuf = [&](int p) { return sm + p * 9216 + 4608; };

    auto loadKV = [&](int kv0, int p) {
        __half* kd = Kbuf(p);
        __half* vd = Vbuf(p);
        #pragma unroll
        for (int i = tid; i < 1024; i += 256) {
            int mat = i >> 9, idx = i & 511;
            int r = idx >> 3, c = (idx & 7) * 8;
            const __half* src = (mat ? Vg : Kg) +
                (size_t)(b * SKV + kv0 + r) * DATTN + h * DHEAD + c;
            __half* dst = (mat ? vd : kd) + r * 72 + c;
            cp16(smem_u32(dst), src);
        }
    };

    // stage Q into sm[0..9216), extract fragments, release for KV buffers
    for (int i = tid; i < 1024; i += 256) {
        int r = i >> 3, c = (i & 7) * 8;
        *reinterpret_cast<uint4*>(&sm[r * 72 + c]) =
            *reinterpret_cast<const uint4*>(
                &Qg[(size_t)(b * SQ + q0 + r) * DATTN + h * DHEAD + c]);
    }
    __syncthreads();

    const int a_r  = warp * 16 + (lane & 7) + (lane & 8);
    const int a_c  = (lane & 16) >> 1;
    const int kb_n = (lane & 7) + ((lane & 16) >> 1);
    const int kb_c = (lane & 8);
    const int vb_k = (lane & 7) + (lane & 8);
    const int vb_d = (lane & 16) >> 1;

    uint32_t qf[4][4];
    const uint32_t qsm = smem_u32(sm);
    #pragma unroll
    for (int ks = 0; ks < 4; ks++)
        ldsm4(qf[ks], qsm + (uint32_t)((a_r * 72 + ks * 16 + a_c) * 2));
    __syncthreads();   // all warps done reading Q before KV overwrites

    loadKV(0, 0);
    cp_commit();

    float of[8][4];
    #pragma unroll
    for (int i = 0; i < 8; i++) { of[i][0]=of[i][1]=of[i][2]=of[i][3]=0.f; }
    float m0 = -1e30f, m1 = -1e30f, l0 = 0.f, l1 = 0.f;

    const int NIT = SKV / 64;
    for (int it = 0; it < NIT; it++) {
        if (it + 1 < NIT) { loadKV((it + 1) * 64, (it + 1) & 1); cp_commit(); cp_wait<1>(); }
        else              { cp_wait<0>(); }
        __syncthreads();

        const uint32_t ksm = smem_u32(Kbuf(it & 1));
        const uint32_t vsm = smem_u32(Vbuf(it & 1));

        // S = Q K^T (log2 units, pre-scaled)
        float sf[8][4];
        #pragma unroll
        for (int i = 0; i < 8; i++) { sf[i][0]=sf[i][1]=sf[i][2]=sf[i][3]=0.f; }
        #pragma unroll
        for (int ks = 0; ks < 4; ks++) {
            uint32_t bf[8][2];
            #pragma unroll
            for (int ntp = 0; ntp < 4; ntp++) {
                uint32_t r[4];
                ldsm4(r, ksm + (uint32_t)(((ntp * 16 + kb_n) * 72 + ks * 16 + kb_c) * 2));
                bf[ntp * 2][0] = r[0]; bf[ntp * 2][1] = r[1];
                bf[ntp * 2 + 1][0] = r[2]; bf[ntp * 2 + 1][1] = r[3];
            }
            #pragma unroll
            for (int nt = 0; nt < 8; nt++) mma16816(sf[nt], qf[ks], bf[nt]);
        }

        // online softmax in log2 domain
        float mx0 = -1e30f, mx1 = -1e30f;
        #pragma unroll
        for (int nt = 0; nt < 8; nt++) {
            mx0 = fmaxf(mx0, fmaxf(sf[nt][0], sf[nt][1]));
            mx1 = fmaxf(mx1, fmaxf(sf[nt][2], sf[nt][3]));
        }
        #pragma unroll
        for (int off = 1; off < 4; off <<= 1) {
            mx0 = fmaxf(mx0, __shfl_xor_sync(0xffffffffu, mx0, off));
            mx1 = fmaxf(mx1, __shfl_xor_sync(0xffffffffu, mx1, off));
        }
        float mn0 = fmaxf(m0, mx0), mn1 = fmaxf(m1, mx1);
        float al0 = ex2(m0 - mn0), al1 = ex2(m1 - mn1);
        float rs0 = 0.f, rs1 = 0.f;
        #pragma unroll
        for (int nt = 0; nt < 8; nt++) {
            sf[nt][0] = ex2(sf[nt][0] - mn0);
            sf[nt][1] = ex2(sf[nt][1] - mn0);
            sf[nt][2] = ex2(sf[nt][2] - mn1);
            sf[nt][3] = ex2(sf[nt][3] - mn1);
            rs0 += sf[nt][0] + sf[nt][1];
            rs1 += sf[nt][2] + sf[nt][3];
        }
        #pragma unroll
        for (int off = 1; off < 4; off <<= 1) {
            rs0 += __shfl_xor_sync(0xffffffffu, rs0, off);
            rs1 += __shfl_xor_sync(0xffffffffu, rs1, off);
        }
        l0 = l0 * al0 + rs0; m0 = mn0;
        l1 = l1 * al1 + rs1; m1 = mn1;
        #pragma unroll
        for (int dt = 0; dt < 8; dt++) {
            of[dt][0] *= al0; of[dt][1] *= al0; of[dt][2] *= al1; of[dt][3] *= al1;
        }

        // O += P V
        #pragma unroll
        for (int j = 0; j < 4; j++) {
            uint32_t pa[4];
            pa[0] = pack_h2(sf[2 * j][0],     sf[2 * j][1]);
            pa[1] = pack_h2(sf[2 * j][2],     sf[2 * j][3]);
            pa[2] = pack_h2(sf[2 * j + 1][0], sf[2 * j + 1][1]);
            pa[3] = pack_h2(sf[2 * j + 1][2], sf[2 * j + 1][3]);
            uint32_t bf[8][2];
            #pragma unroll
            for (int p = 0; p < 4; p++) {
                uint32_t r[4];
                ldsm4t(r, vsm + (uint32_t)(((j * 16 + vb_k) * 72 + p * 16 + vb_d) * 2));
                bf[p * 2][0] = r[0]; bf[p * 2][1] = r[1];
                bf[p * 2 + 1][0] = r[2]; bf[p * 2 + 1][1] = r[3];
            }
            #pragma unroll
            for (int dt = 0; dt < 8; dt++) mma16816(of[dt], pa, bf[dt]);
        }
        __syncthreads();
    }

    float inv0 = 1.f / l0, inv1 = 1.f / l1;
    const int r0 = b * SQ + q0 + warp * 16 + (lane >> 2);
    const int cb = h * DHEAD + 2 * (lane & 3);
    #pragma unroll
    for (int dt = 0; dt < 8; dt++) {
        int c = cb + dt * 8;
        *reinterpret_cast<__half2*>(&Og[(size_t)r0 * DATTN + c]) =
            __floats2half2_rn(of[dt][0] * inv0, of[dt][1] * inv0);
        *reinterpret_cast<__half2*>(&Og[(size_t)(r0 + 8) * DATTN + c]) =
            __floats2half2_rn(of[dt][2] * inv1, of[dt][3] * inv1);
    }
}

// --------------------------- launch ------------------------------------------
extern "C" void kernel_launch(void* const* d_in, const int* in_sizes, int n_in,
                              void* d_out, int out_size) {
    (void)in_sizes; (void)n_in; (void)out_size;
    const float* x    = (const float*)d_in[0];
    const float* cond = (const float*)d_in[1];
    const float* wq   = (const float*)d_in[2];
    const float* wk   = (const float*)d_in[3];
    const float* wv   = (const float*)d_in[4];
    const float* wo   = (const float*)d_in[5];
    const float* bo   = (const float*)d_in[6];

    __half *xh, *ch, *wqh, *wkh, *wvh, *woh, *Qb, *Kb, *Vb, *AOb;
    cudaGetSymbolAddress((void**)&xh,  g_xh);
    cudaGetSymbolAddress((void**)&ch,  g_ch);
    cudaGetSymbolAddress((void**)&wqh, g_wq);
    cudaGetSymbolAddress((void**)&wkh, g_wk);
    cudaGetSymbolAddress((void**)&wvh, g_wv);
    cudaGetSymbolAddress((void**)&woh, g_wo);
    cudaGetSymbolAddress((void**)&Qb,  g_Q);
    cudaGetSymbolAddress((void**)&Kb,  g_K);
    cudaGetSymbolAddress((void**)&Vb,  g_V);
    cudaGetSymbolAddress((void**)&AOb, g_AO);

    const float QSCALE = 0.125f * 1.44269504088896f;  // d^-0.5 * log2(e)

    convert_all<<<(C_N5 + 255) / 256, 256>>>(x, cond, wq, wk, wv, wo,
                                             xh, ch, wqh, wkh, wvh, woh, QSCALE);

    // fused Q/K/V projections: z=0 -> x@wq (K=1024); z=1 -> cond@wk; z=2 -> cond@wv (K=768)
    dim3 gqkv(DATTN / 128, MROWS / 128, 3);   // (8, 32, 3)
    gemm_hmma<0, 0, 1><<<gqkv, 256>>>(xh, ch, wqh, wkh, wvh,
                                      Qb, Kb, Vb, nullptr,
                                      MROWS, DATTN, DMODEL, DCOND);

    flash_attn<<<dim3(SQ / 128, NHEADS, B_SZ), 256>>>(Qb, Kb, Vb, AOb);

    dim3 gout(DMODEL / 128, MROWS / 128, 1);
    gemm_hmma<1, 1, 0><<<gout, 256>>>(AOb, nullptr, woh, nullptr, nullptr,
                                      d_out, nullptr, nullptr, bo,
                                      MROWS, DMODEL, DATTN, DATTN);
}